// round 15
// baseline (speedup 1.0000x reference)
#include <cuda_runtime.h>
#include <math.h>

#define NN   2048
#define BB   8
#define HH   4
#define DD   64
#define SEG1 (BB*HH)     // 32 segments in layer 1
#define CH   64          // scan chunks per segment
#define CL   (NN/CH)     // 32 elements per chunk
#define NCPB 2           // chunks per scan block
#define ALPHA_ 0.2f

// ---------------- scratch (static __device__, no allocation) ----------------
__device__ float g_Hbuf [SEG1 * NN * DD];
__device__ float g_H2   [BB   * NN * DD];
__device__ float g_s1   [SEG1 * NN];
__device__ float g_s2   [SEG1 * NN];
__device__ float g_sorted[SEG1 * NN];
__device__ int   g_perm [SEG1 * NN];
__device__ float g_wpre [SEG1 * NN];
__device__ float g_wsuf [SEG1 * NN];
__device__ float g_smax [SEG1];
__device__ float g_CT   [SEG1 * CH * 128];     // chunk totals (A: 0-63, B: 64-127)
__device__ float g_OFF  [SEG1 * CH * 128];     // chunk offsets (A prefix, B suffix)
__device__ float g_Ah   [SEG1 * (NN+1) * DD];  // RELATIVE prefix within chunk
__device__ float g_Bh   [SEG1 * (NN+1) * DD];  // RELATIVE suffix within chunk
__device__ float g_XC   [BB * NN * HH * DD];
__device__ int   g_qp   [SEG1 * NN];
__device__ float2 g_qr  [SEG1 * NN];

// ---------------- layer-1 GEMM: all 4 heads per block, X tile reused ----------------
__global__ __launch_bounds__(256)
void gemm1_kernel(const float* __restrict__ X,
                  const float* __restrict__ Wmat,
                  const float* __restrict__ avec) {
    __shared__ float XsT[64][68];
    __shared__ float Ws [64][64];
    const int tid = threadIdx.x;
    const int R0  = blockIdx.x * 64;
    const int rq  = tid >> 4;
    const int cq  = tid & 15;

#pragma unroll
    for (int i = 0; i < 16; i++) {
        int idx = tid + i * 256;
        int r = idx >> 6, k = idx & 63;
        XsT[k][r] = X[(size_t)(R0 + r) * 64 + k];
    }

    for (int head = 0; head < HH; head++) {
        __syncthreads();
#pragma unroll
        for (int i = 0; i < 16; i++) {
            int idx = tid + i * 256;
            int k = idx >> 6, d = idx & 63;
            Ws[k][d] = Wmat[((size_t)head * 64 + k) * 64 + d];
        }
        __syncthreads();

        float acc[4][4];
#pragma unroll
        for (int i = 0; i < 4; i++)
#pragma unroll
            for (int j = 0; j < 4; j++) acc[i][j] = 0.f;

#pragma unroll 16
        for (int k = 0; k < 64; k++) {
            float4 xv = *(const float4*)&XsT[k][rq * 4];
            float4 wv = *(const float4*)&Ws [k][cq * 4];
            acc[0][0] += xv.x*wv.x; acc[0][1] += xv.x*wv.y; acc[0][2] += xv.x*wv.z; acc[0][3] += xv.x*wv.w;
            acc[1][0] += xv.y*wv.x; acc[1][1] += xv.y*wv.y; acc[1][2] += xv.y*wv.z; acc[1][3] += xv.y*wv.w;
            acc[2][0] += xv.z*wv.x; acc[2][1] += xv.z*wv.y; acc[2][2] += xv.z*wv.z; acc[2][3] += xv.z*wv.w;
            acc[3][0] += xv.w*wv.x; acc[3][1] += xv.w*wv.y; acc[3][2] += xv.w*wv.z; acc[3][3] += xv.w*wv.w;
        }

        float a1v[4], a2v[4];
#pragma unroll
        for (int j = 0; j < 4; j++) {
            a1v[j] = __ldg(&avec[head * 128 + cq * 4 + j]);
            a2v[j] = __ldg(&avec[head * 128 + 64 + cq * 4 + j]);
        }
#pragma unroll
        for (int i = 0; i < 4; i++) {
            int R = R0 + rq * 4 + i;
            int g = R >> 11;
            int n = R & (NN - 1);
            int seg = g * HH + head;
            size_t base = ((size_t)seg * NN + n) * 64 + cq * 4;
            float4 v; v.x = acc[i][0]; v.y = acc[i][1]; v.z = acc[i][2]; v.w = acc[i][3];
            *(float4*)&g_Hbuf[base] = v;

            float p1 = acc[i][0]*a1v[0] + acc[i][1]*a1v[1] + acc[i][2]*a1v[2] + acc[i][3]*a1v[3];
            float p2 = acc[i][0]*a2v[0] + acc[i][1]*a2v[1] + acc[i][2]*a2v[2] + acc[i][3]*a2v[3];
#pragma unroll
            for (int off = 8; off; off >>= 1) {
                p1 += __shfl_down_sync(0xffffffffu, p1, off, 16);
                p2 += __shfl_down_sync(0xffffffffu, p2, off, 16);
            }
            if (cq == 0) {
                g_s1[seg * NN + n] = p1;
                g_s2[seg * NN + n] = p2;
            }
        }
    }
}

// ---------------- layer-2 GEMM (K = 256) ----------------
__global__ __launch_bounds__(256)
void gemm2_kernel(const float* __restrict__ Wmat,
                  const float* __restrict__ avec) {
    __shared__ float XsT[64][68];
    __shared__ float Ws [64][64];
    const int tid = threadIdx.x;
    const int R0  = blockIdx.x * 64;
    const int rq  = tid >> 4;
    const int cq  = tid & 15;

    float acc[4][4];
#pragma unroll
    for (int i = 0; i < 4; i++)
#pragma unroll
        for (int j = 0; j < 4; j++) acc[i][j] = 0.f;

    for (int kp = 0; kp < 256; kp += 64) {
        __syncthreads();
#pragma unroll
        for (int i = 0; i < 16; i++) {
            int idx = tid + i * 256;
            int r = idx >> 6, k = idx & 63;
            XsT[k][r] = g_XC[(size_t)(R0 + r) * 256 + kp + k];
        }
#pragma unroll
        for (int i = 0; i < 16; i++) {
            int idx = tid + i * 256;
            int k = idx >> 6, d = idx & 63;
            Ws[k][d] = Wmat[((size_t)kp + k) * 64 + d];
        }
        __syncthreads();
#pragma unroll 16
        for (int k = 0; k < 64; k++) {
            float4 xv = *(const float4*)&XsT[k][rq * 4];
            float4 wv = *(const float4*)&Ws [k][cq * 4];
            acc[0][0] += xv.x*wv.x; acc[0][1] += xv.x*wv.y; acc[0][2] += xv.x*wv.z; acc[0][3] += xv.x*wv.w;
            acc[1][0] += xv.y*wv.x; acc[1][1] += xv.y*wv.y; acc[1][2] += xv.y*wv.z; acc[1][3] += xv.y*wv.w;
            acc[2][0] += xv.z*wv.x; acc[2][1] += xv.z*wv.y; acc[2][2] += xv.z*wv.z; acc[2][3] += xv.z*wv.w;
            acc[3][0] += xv.w*wv.x; acc[3][1] += xv.w*wv.y; acc[3][2] += xv.w*wv.z; acc[3][3] += xv.w*wv.w;
        }
    }

    float a1v[4], a2v[4];
#pragma unroll
    for (int j = 0; j < 4; j++) {
        a1v[j] = __ldg(&avec[cq * 4 + j]);
        a2v[j] = __ldg(&avec[64 + cq * 4 + j]);
    }
#pragma unroll
    for (int i = 0; i < 4; i++) {
        int R = R0 + rq * 4 + i;
        int seg = R >> 11;
        int n = R & (NN - 1);
        size_t base = ((size_t)seg * NN + n) * 64 + cq * 4;
        float4 v; v.x = acc[i][0]; v.y = acc[i][1]; v.z = acc[i][2]; v.w = acc[i][3];
        *(float4*)&g_H2[base] = v;

        float p1 = acc[i][0]*a1v[0] + acc[i][1]*a1v[1] + acc[i][2]*a1v[2] + acc[i][3]*a1v[3];
        float p2 = acc[i][0]*a2v[0] + acc[i][1]*a2v[1] + acc[i][2]*a2v[2] + acc[i][3]*a2v[3];
#pragma unroll
        for (int off = 8; off; off >>= 1) {
            p1 += __shfl_down_sync(0xffffffffu, p1, off, 16);
            p2 += __shfl_down_sync(0xffffffffu, p2, off, 16);
        }
        if (cq == 0) {
            g_s1[seg * NN + n] = p1;
            g_s2[seg * NN + n] = p2;
        }
    }
}

// ---------------- hybrid bitonic sort: smem stages j>=64, register/shuffle j<=32 ----------------
__device__ __forceinline__ void bitonic_shfl_stage(float& v0, float& v1, int& i0, int& i1,
                                                   int e0, int k, int j) {
    int lm = j >> 1;
    float u0 = __shfl_xor_sync(0xffffffffu, v0, lm);
    float u1 = __shfl_xor_sync(0xffffffffu, v1, lm);
    int   a0 = __shfl_xor_sync(0xffffffffu, i0, lm);
    int   a1 = __shfl_xor_sync(0xffffffffu, i1, lm);
    bool up      = ((e0 & k) == 0);
    bool lower   = ((e0 & j) == 0);
    bool keepmin = (lower == up);
    if (keepmin ? (v0 > u0) : (v0 < u0)) { v0 = u0; i0 = a0; }
    if (keepmin ? (v1 > u1) : (v1 < u1)) { v1 = u1; i1 = a1; }
}

__global__ __launch_bounds__(1024)
void sort_kernel() {
    __shared__ float key[NN];
    __shared__ int   idx[NN];
    const int seg = blockIdx.x, tid = threadIdx.x;
    const int e0 = tid * 2, e1 = e0 + 1;

    key[tid]        = g_s2[seg * NN + tid];        idx[tid]        = tid;
    key[tid + 1024] = g_s2[seg * NN + tid + 1024]; idx[tid + 1024] = tid + 1024;
    __syncthreads();

    float v0, v1; int i0, i1;

    // ---- k = 2..64 entirely in registers (warp owns 64 contiguous elements) ----
    v0 = key[e0]; v1 = key[e1]; i0 = idx[e0]; i1 = idx[e1];
#pragma unroll
    for (int k = 2; k <= 64; k <<= 1) {
#pragma unroll
        for (int j = k >> 1; j >= 2; j >>= 1)
            bitonic_shfl_stage(v0, v1, i0, i1, e0, k, j);
        {   // j = 1: in-thread
            bool up = ((e0 & k) == 0);
            if ((v0 > v1) == up) {
                float tv = v0; v0 = v1; v1 = tv;
                int ti = i0; i0 = i1; i1 = ti;
            }
        }
    }
    key[e0] = v0; key[e1] = v1; idx[e0] = i0; idx[e1] = i1;
    __syncthreads();

    // ---- k = 128..2048: smem stages for j>=64, register stages for j<=32 ----
    for (int k = 128; k <= NN; k <<= 1) {
        for (int j = k >> 1; j >= 64; j >>= 1) {
            int i = ((tid & ~(j - 1)) << 1) | (tid & (j - 1));
            int p = i | j;
            bool up = ((i & k) == 0);
            float ka = key[i], kb = key[p];
            if ((ka > kb) == up) {
                key[i] = kb; key[p] = ka;
                int t = idx[i]; idx[i] = idx[p]; idx[p] = t;
            }
            __syncthreads();
        }
        v0 = key[e0]; v1 = key[e1]; i0 = idx[e0]; i1 = idx[e1];
#pragma unroll
        for (int j = 32; j >= 2; j >>= 1)
            bitonic_shfl_stage(v0, v1, i0, i1, e0, k, j);
        {
            bool up = ((e0 & k) == 0);
            if ((v0 > v1) == up) {
                float tv = v0; v0 = v1; v1 = tv;
                int ti = i0; i0 = i1; i1 = ti;
            }
        }
        key[e0] = v0; key[e1] = v1; idx[e0] = i0; idx[e1] = i1;
        __syncthreads();
    }

    float smaxv = key[NN - 1];
#pragma unroll
    for (int u = 0; u < 2; u++) {
        int i = tid + u * 1024;
        float kk = key[i];
        g_sorted[seg * NN + i] = kk;
        g_perm  [seg * NN + i] = idx[i];
        g_wsuf  [seg * NN + i] = expf(kk - smaxv);
        g_wpre  [seg * NN + i] = expf(ALPHA_ * (kk - smaxv));
    }
    if (tid == 0) g_smax[seg] = smaxv;
}

// ---------------- scan: relative prefix/suffix + chunk totals (replaces 3a + 3c) ----------------
__global__ __launch_bounds__(128)
void scan_kernel(int layer) {
    const int seg = blockIdx.x, cb = blockIdx.y * NCPB, tid = threadIdx.x;
    const float* __restrict__ Hmat = (layer == 1) ? g_Hbuf : g_H2;

    __shared__ int   sp [NCPB * CL];
    __shared__ float swA[NCPB * CL], swB[NCPB * CL];
    __shared__ float tile[NCPB * CL * 64];   // 16KB

    if (tid < NCPB * CL) {
        sp [tid] = g_perm[seg * NN + cb * CL + tid];
        swA[tid] = g_wpre[seg * NN + cb * CL + tid];
        swB[tid] = g_wsuf[seg * NN + cb * CL + tid];
    }
    __syncthreads();

    const size_t segNN = (size_t)seg * NN;
    {
        int rg = tid >> 4;        // 0..7
        int cq = tid & 15;        // float4 slot
#pragma unroll
        for (int rr = 0; rr < NCPB * CL; rr += 8) {
            int r = rr + rg;
            const float4* src = (const float4*)&Hmat[(segNN + sp[r]) * 64];
            ((float4*)&tile[r * 64])[cq] = __ldg(&src[cq]);
        }
    }
    __syncthreads();

    const int ci   = tid >> 6;           // chunk within block
    const int half = (tid >> 5) & 1;     // 0 = A (forward), 1 = B (backward)
    const int d2   = (tid & 31) * 2;
    const int c    = cb + ci;
    const float* tl = &tile[ci * CL * 64];
    const float* w  = half ? &swB[ci * CL] : &swA[ci * CL];
    const size_t rowbase = ((size_t)seg * (NN + 1) + c * CL) * 64 + d2;

    float2 run = make_float2(0.f, 0.f);
    if (half == 0) {   // forward exclusive prefix (relative to chunk start)
#pragma unroll 8
        for (int t = 0; t < CL; t++) {
            *(float2*)&g_Ah[rowbase + (size_t)t * 64] = run;
            float2 h = *(const float2*)&tl[t * 64 + d2];
            run.x += w[t] * h.x;
            run.y += w[t] * h.y;
        }
        *(float2*)&g_CT[(seg * CH + c) * 128 + d2] = run;          // chunk total
        if (c == CH - 1)   // row p == NN belongs to last chunk: full-chunk prefix
            *(float2*)&g_Ah[((size_t)seg * (NN + 1) + NN) * 64 + d2] = run;
    } else {           // reverse inclusive suffix (relative within chunk)
        if (c == CH - 1)   // row p == NN: empty suffix
            *(float2*)&g_Bh[((size_t)seg * (NN + 1) + NN) * 64 + d2] = run;
#pragma unroll 8
        for (int t = CL - 1; t >= 0; t--) {
            float2 h = *(const float2*)&tl[t * 64 + d2];
            run.x += w[t] * h.x;
            run.y += w[t] * h.y;
            *(float2*)&g_Bh[rowbase + (size_t)t * 64] = run;
        }
        *(float2*)&g_CT[(seg * CH + c) * 128 + 64 + d2] = run;     // chunk total
    }
}

// ---------------- qprep: scalar scans + binary search + chunk-offset table ----------------
__global__ __launch_bounds__(1024)
void qprep_kernel() {
    const int seg = blockIdx.x, tid = threadIdx.x;
    const int lane = tid & 31, wid = tid >> 5;

    __shared__ float srt[NN];
    __shared__ float sA1[NN + 1];
    __shared__ float sB1[NN + 1];
    __shared__ float wxA[32], wxB[32];

    srt[tid]        = g_sorted[seg * NN + tid];
    srt[tid + 1024] = g_sorted[seg * NN + tid + 1024];

    const int j0 = tid * 2;
    float2 wa = *(const float2*)&g_wpre[seg * NN + j0];
    float2 wb = *(const float2*)&g_wsuf[seg * NN + j0];
    float sa = wa.x + wa.y;
    float sb = wb.x + wb.y;

    float xa = sa;
#pragma unroll
    for (int off = 1; off < 32; off <<= 1) {
        float y = __shfl_up_sync(0xffffffffu, xa, off);
        if (lane >= off) xa += y;
    }
    float exA = xa - sa;
    float xb = sb;
#pragma unroll
    for (int off = 1; off < 32; off <<= 1) {
        float y = __shfl_down_sync(0xffffffffu, xb, off);
        if (lane < 32 - off) xb += y;
    }
    float exB = xb - sb;

    if (lane == 31) wxA[wid] = xa;
    if (lane == 0)  wxB[wid] = xb;
    __syncthreads();
    if (wid == 0) {
        float va = wxA[lane];
        float xa2 = va;
#pragma unroll
        for (int off = 1; off < 32; off <<= 1) {
            float y = __shfl_up_sync(0xffffffffu, xa2, off);
            if (lane >= off) xa2 += y;
        }
        float vb = wxB[lane];
        float xb2 = vb;
#pragma unroll
        for (int off = 1; off < 32; off <<= 1) {
            float y = __shfl_down_sync(0xffffffffu, xb2, off);
            if (lane < 32 - off) xb2 += y;
        }
        __syncwarp();
        wxA[lane] = xa2 - va;
        wxB[lane] = xb2 - vb;
        if (lane == 31) sA1[NN] = xa2;
        if (lane == 0)  sB1[NN] = 0.f;
    }
    __syncthreads();
    float oa = wxA[wid] + exA;
    float ob = wxB[wid] + exB;
    sA1[j0]     = oa;
    sA1[j0 + 1] = oa + wa.x;
    sB1[j0]     = ob + wb.x + wb.y;
    sB1[j0 + 1] = ob + wb.y;
    __syncthreads();

    const float smax = g_smax[seg];
#pragma unroll
    for (int u = 0; u < 2; u++) {
        int n = tid + u * 1024;
        float s1v = g_s1[seg * NN + n];
        float uu = s1v + smax;
        float m = (uu >= 0.f) ? uu : ALPHA_ * uu;
        float f1 = expf(uu - m);
        float f2 = expf(ALPHA_ * uu - m);
        float tau = -s1v;
        int lo = 0, hi = NN;
        while (lo < hi) {
            int mid = (lo + hi) >> 1;
            if (srt[mid] < tau) lo = mid + 1; else hi = mid;
        }
        int p = lo;
        float den = f1 * sB1[p] + f2 * sA1[p];
        g_qp[seg * NN + n] = p;
        g_qr[seg * NN + n] = make_float2(f2 / den, f1 / den);
    }

    // chunk-offset table from scan totals (threads 0-127, hidden behind other warps)
    if (tid < 64) {
        int d = tid;
        float off = 0.f;
        for (int c = 0; c < CH; c++) {
            g_OFF[(seg * CH + c) * 128 + d] = off;
            off += g_CT[(seg * CH + c) * 128 + d];
        }
    } else if (tid < 128) {
        int d = tid - 64;
        float off = 0.f;
        for (int c = CH - 1; c >= 0; c--) {
            g_OFF[(seg * CH + c) * 128 + 64 + d] = off;
            off += g_CT[(seg * CH + c) * 128 + 64 + d];
        }
    }
}

// ---------------- layer-1 combine: stream + offset add, elu -> XC ----------------
__global__ __launch_bounds__(256)
void combine1_kernel() {
    const int seg = blockIdx.y, tid = threadIdx.x;
    const int n  = blockIdx.x * 16 + (tid >> 4);
    const int d4 = (tid & 15) * 4;

    int    p = g_qp[seg * NN + n];
    int    c = p >> 5; if (c > CH - 1) c = CH - 1;   // CL == 32
    float2 r = g_qr[seg * NN + n];
    size_t rb = ((size_t)seg * (NN + 1) + p) * 64 + d4;
    float4 a  = *(const float4*)&g_Ah[rb];
    float4 b  = *(const float4*)&g_Bh[rb];
    float4 oa = *(const float4*)&g_OFF[(seg * CH + c) * 128 + d4];
    float4 ob = *(const float4*)&g_OFF[(seg * CH + c) * 128 + 64 + d4];
    a.x += oa.x; a.y += oa.y; a.z += oa.z; a.w += oa.w;
    b.x += ob.x; b.y += ob.y; b.z += ob.z; b.w += ob.w;
    float4 o;
    o.x = r.y * b.x + r.x * a.x;
    o.y = r.y * b.y + r.x * a.y;
    o.z = r.y * b.z + r.x * a.z;
    o.w = r.y * b.w + r.x * a.w;
    o.x = (o.x > 0.f) ? o.x : expm1f(o.x);
    o.y = (o.y > 0.f) ? o.y : expm1f(o.y);
    o.z = (o.z > 0.f) ? o.z : expm1f(o.z);
    o.w = (o.w > 0.f) ? o.w : expm1f(o.w);

    int g = seg >> 2, h = seg & 3;
    *(float4*)&g_XC[((size_t)g * NN + n) * (HH * DD) + h * DD + d4] = o;
}

// ---------------- layer-2 combine: stream + offset add, elu -> log_softmax -> out ----------------
__global__ __launch_bounds__(256)
void combine2_kernel(float* __restrict__ out) {
    const int seg = blockIdx.y, tid = threadIdx.x;
    const int n  = blockIdx.x * 16 + (tid >> 4);
    const int d4 = (tid & 15) * 4;

    int    p = g_qp[seg * NN + n];
    int    c = p >> 5; if (c > CH - 1) c = CH - 1;
    float2 r = g_qr[seg * NN + n];
    size_t rb = ((size_t)seg * (NN + 1) + p) * 64 + d4;
    float4 a  = *(const float4*)&g_Ah[rb];
    float4 b  = *(const float4*)&g_Bh[rb];
    float4 oa = *(const float4*)&g_OFF[(seg * CH + c) * 128 + d4];
    float4 ob = *(const float4*)&g_OFF[(seg * CH + c) * 128 + 64 + d4];
    a.x += oa.x; a.y += oa.y; a.z += oa.z; a.w += oa.w;
    b.x += ob.x; b.y += ob.y; b.z += ob.z; b.w += ob.w;
    float4 o;
    o.x = r.y * b.x + r.x * a.x;
    o.y = r.y * b.y + r.x * a.y;
    o.z = r.y * b.z + r.x * a.z;
    o.w = r.y * b.w + r.x * a.w;
    o.x = (o.x > 0.f) ? o.x : expm1f(o.x);
    o.y = (o.y > 0.f) ? o.y : expm1f(o.y);
    o.z = (o.z > 0.f) ? o.z : expm1f(o.z);
    o.w = (o.w > 0.f) ? o.w : expm1f(o.w);

    float lm = fmaxf(fmaxf(o.x, o.y), fmaxf(o.z, o.w));
#pragma unroll
    for (int off = 8; off; off >>= 1)
        lm = fmaxf(lm, __shfl_xor_sync(0xffffffffu, lm, off, 16));
    float ls = expf(o.x - lm) + expf(o.y - lm) + expf(o.z - lm) + expf(o.w - lm);
#pragma unroll
    for (int off = 8; off; off >>= 1)
        ls += __shfl_xor_sync(0xffffffffu, ls, off, 16);
    float sub = lm + logf(ls);

    float4 w;
    w.x = o.x - sub; w.y = o.y - sub; w.z = o.z - sub; w.w = o.w - sub;
    *(float4*)&out[((size_t)seg * NN + n) * DD + d4] = w;
}

// ---------------- launch ----------------
extern "C" void kernel_launch(void* const* d_in, const int* in_sizes, int n_in,
                              void* d_out, int out_size) {
    const float* h_states = (const float*)d_in[0];
    const float* W_heads  = (const float*)d_in[1];
    const float* a_heads  = (const float*)d_in[2];
    const float* W_out    = (const float*)d_in[3];
    const float* a_out    = (const float*)d_in[4];
    float* out = (float*)d_out;

    // ---- layer 1 ----
    gemm1_kernel<<<BB * NN / 64, 256>>>(h_states, W_heads, a_heads);
    sort_kernel<<<SEG1, 1024>>>();
    scan_kernel<<<dim3(SEG1, CH / NCPB), 128>>>(1);
    qprep_kernel<<<SEG1, 1024>>>();
    combine1_kernel<<<dim3(NN / 16, SEG1), 256>>>();

    // ---- layer 2 ----
    gemm2_kernel<<<BB * NN / 64, 256>>>(W_out, a_out);
    sort_kernel<<<BB, 1024>>>();
    scan_kernel<<<dim3(BB, CH / NCPB), 128>>>(2);
    qprep_kernel<<<BB, 1024>>>();
    combine2_kernel<<<dim3(NN / 16, BB), 256>>>(out);
}